// round 2
// baseline (speedup 1.0000x reference)
#include <cuda_runtime.h>
#include <math.h>

#define T_STEPS 240
#define BATCH   240
#define INPUTD  256
#define HID     1024
#define NSTEPS  30
#define OUTD    8
#define WW      240

// ---------------- device scratch (no allocations allowed) ----------------
__device__ float g_h[2][BATCH * HID];   // ping-pong LSTM hidden
__device__ float g_c[BATCH * HID];      // LSTM cell
__device__ float g_bias[4 * HID];       // bih + bhh precomputed
__device__ float g_u[OUTD];             // decoder "u" (prev logp)
__device__ float g_hdec[HID];           // decoder GRU hidden
__device__ float g_applied[HID];        // attention-applied context
__device__ float g_comb[HID];           // relu(comb)
__device__ float g_gi[3 * HID];
__device__ float g_gh[3 * HID];

__device__ __forceinline__ float sigf(float x) { return 1.f / (1.f + expf(-x)); }

__device__ __forceinline__ float warp_red(float s) {
#pragma unroll
    for (int o = 16; o; o >>= 1) s += __shfl_down_sync(0xffffffffu, s, o);
    return s;
}

// ---------------- init: zero state, precompute bias sum ----------------
__global__ void k_init(const float* __restrict__ bih, const float* __restrict__ bhh) {
    int i = blockIdx.x * blockDim.x + threadIdx.x;
    int n = BATCH * HID;
    for (int j = i; j < n; j += gridDim.x * blockDim.x) {
        g_h[0][j] = 0.f;
        g_c[j]    = 0.f;
    }
    if (i < 4 * HID) g_bias[i] = bih[i] + bhh[i];
}

// ---------------- fused LSTM step: G = h@Whh^T + x@Wih^T + b, gate update ---
// Block tile: BM=48 batch rows x BN=32 hidden units (x 4 gates).
// 128 threads: tx in [0,16) -> cols {tx, tx+16}; ty in [0,8) -> rows {ty+8r}.
#define BM 48
#define BN 32
#define KT 32

__global__ __launch_bounds__(128, 2) void k_lstm_step(
    const float* __restrict__ data,   // [T][B][INPUTD]
    const float* __restrict__ Whh,    // [4H][H]
    const float* __restrict__ Wih,    // [4H][INPUTD]
    int t)
{
    const int par = t & 1;
    const float* __restrict__ h_in  = g_h[par];
    float* __restrict__ h_out       = g_h[par ^ 1];
    const float* __restrict__ x_t   = data + (size_t)t * BATCH * INPUTD;

    __shared__ float As[KT][BM + 1];        // A^T tile (k-major)
    __shared__ float Bs[4][KT][BN + 1];     // weight tiles per gate

    const int m0  = blockIdx.y * BM;
    const int n0  = blockIdx.x * BN;
    const int tid = threadIdx.x;
    const int tx  = tid & 15;
    const int ty  = tid >> 4;

    float acc[6][2][4];
#pragma unroll
    for (int r = 0; r < 6; r++)
#pragma unroll
        for (int c2 = 0; c2 < 2; c2++)
#pragma unroll
            for (int g = 0; g < 4; g++) acc[r][c2][g] = 0.f;

#pragma unroll
    for (int phase = 0; phase < 2; ++phase) {
        const float* __restrict__ A = phase ? x_t : h_in;
        const float* __restrict__ W = phase ? Wih : Whh;
        const int K = phase ? INPUTD : HID;

        for (int k0 = 0; k0 < K; k0 += KT) {
            __syncthreads();
            // A tile: coalesced (32 consecutive k per warp), conflict-free store
#pragma unroll
            for (int i = tid; i < BM * KT; i += 128) {
                int m = i >> 5;
                int k = i & 31;
                As[k][m] = A[(size_t)(m0 + m) * K + k0 + k];
            }
            // B tiles for 4 gates
#pragma unroll
            for (int i = tid; i < 4 * BN * KT; i += 128) {
                int k = i & 31;
                int c = (i >> 5) & 31;
                int g = i >> 10;
                Bs[g][k][c] = W[(size_t)(g * HID + n0 + c) * K + k0 + k];
            }
            __syncthreads();

#pragma unroll
            for (int k = 0; k < KT; k++) {
                float a[6];
#pragma unroll
                for (int r = 0; r < 6; r++) a[r] = As[k][ty + 8 * r];
                float b[2][4];
#pragma unroll
                for (int c2 = 0; c2 < 2; c2++)
#pragma unroll
                    for (int g = 0; g < 4; g++) b[c2][g] = Bs[g][k][tx + 16 * c2];
#pragma unroll
                for (int r = 0; r < 6; r++)
#pragma unroll
                    for (int c2 = 0; c2 < 2; c2++)
#pragma unroll
                        for (int g = 0; g < 4; g++)
                            acc[r][c2][g] += a[r] * b[c2][g];
            }
        }
    }

    // gate epilogue: i,f,g,o ordering per reference split
#pragma unroll
    for (int r = 0; r < 6; r++) {
        int m = m0 + ty + 8 * r;
#pragma unroll
        for (int c2 = 0; c2 < 2; c2++) {
            int n = n0 + tx + 16 * c2;
            float gi = acc[r][c2][0] + g_bias[n];
            float gf = acc[r][c2][1] + g_bias[HID + n];
            float gg = acc[r][c2][2] + g_bias[2 * HID + n];
            float go = acc[r][c2][3] + g_bias[3 * HID + n];
            size_t idx = (size_t)m * HID + n;
            float cn = sigf(gf) * g_c[idx] + sigf(gi) * tanhf(gg);
            g_c[idx] = cn;
            h_out[idx] = sigf(go) * tanhf(cn);
        }
    }
}

// ---------------- decoder ----------------
__global__ void k_hdec_init() {
    int i = blockIdx.x * blockDim.x + threadIdx.x;
    if (i < HID) g_hdec[i] = g_h[0][(size_t)(BATCH - 1) * HID + i];
    if (i < OUTD) g_u[i] = 1.f / OUTD;
}

// attention: scores -> softmax -> applied = aw @ ctx. One block, 256 threads.
__global__ void k_attn(const float* __restrict__ attn_W, const float* __restrict__ attn_b) {
    __shared__ float v[HID + OUTD];
    __shared__ float sc[WW];
    __shared__ float sinv;
    const int tid = threadIdx.x;

    for (int i = tid; i < OUTD; i += 256) v[i] = g_u[i];
    for (int i = tid; i < HID; i += 256) v[OUTD + i] = g_hdec[i];
    __syncthreads();

    const int warp = tid >> 5, lane = tid & 31;
    for (int j = warp; j < WW; j += 8) {
        const float* __restrict__ row = attn_W + (size_t)j * (HID + OUTD);
        float s = 0.f;
        for (int k = lane; k < HID + OUTD; k += 32) s += row[k] * v[k];
        s = warp_red(s);
        if (!lane) sc[j] = s + attn_b[j];
    }
    __syncthreads();
    if (tid == 0) {
        float mx = -1e30f;
        for (int j = 0; j < WW; j++) mx = fmaxf(mx, sc[j]);
        float sum = 0.f;
        for (int j = 0; j < WW; j++) { float e = expf(sc[j] - mx); sc[j] = e; sum += e; }
        sinv = 1.f / sum;
    }
    __syncthreads();
    const float inv = sinv;
    const float* __restrict__ ctx = g_h[0];
    for (int n = tid; n < HID; n += 256) {
        float s = 0.f;
        for (int j = 0; j < WW; j++) s += sc[j] * ctx[(size_t)j * HID + n];
        g_applied[n] = s * inv;
    }
}

// comb = relu(comb_W @ [u; applied] + comb_b), warp per output row
__global__ void k_comb(const float* __restrict__ comb_W, const float* __restrict__ comb_b) {
    int warp = (blockIdx.x * blockDim.x + threadIdx.x) >> 5;
    int lane = threadIdx.x & 31;
    if (warp >= HID) return;
    const float* __restrict__ row = comb_W + (size_t)warp * (HID + OUTD);
    float s = 0.f;
    if (lane < OUTD) s += row[lane] * g_u[lane];
    for (int k = lane; k < HID; k += 32) s += row[OUTD + k] * g_applied[k];
    s = warp_red(s);
    if (!lane) g_comb[warp] = fmaxf(s + comb_b[warp], 0.f);
}

// gi = Wih_g @ comb + bih ; gh = Whh_g @ hdec + bhh. Warp per row, 6144 rows.
__global__ void k_gru_mv(const float* __restrict__ Wih, const float* __restrict__ Whh,
                         const float* __restrict__ bih, const float* __restrict__ bhh) {
    int warp = (blockIdx.x * blockDim.x + threadIdx.x) >> 5;
    int lane = threadIdx.x & 31;
    if (warp < 3 * HID) {
        const float* __restrict__ row = Wih + (size_t)warp * HID;
        float s = 0.f;
        for (int k = lane; k < HID; k += 32) s += row[k] * g_comb[k];
        s = warp_red(s);
        if (!lane) g_gi[warp] = s + bih[warp];
    } else {
        int r = warp - 3 * HID;
        const float* __restrict__ row = Whh + (size_t)r * HID;
        float s = 0.f;
        for (int k = lane; k < HID; k += 32) s += row[k] * g_hdec[k];
        s = warp_red(s);
        if (!lane) g_gh[r] = s + bhh[r];
    }
}

__global__ void k_gate() {
    int n = blockIdx.x * blockDim.x + threadIdx.x;
    if (n >= HID) return;
    float r  = sigf(g_gi[n] + g_gh[n]);
    float z  = sigf(g_gi[HID + n] + g_gh[HID + n]);
    float nn = tanhf(g_gi[2 * HID + n] + r * g_gh[2 * HID + n]);
    g_hdec[n] = (1.f - z) * nn + z * g_hdec[n];
}

// logits -> log_softmax -> outs[step], update g_u. One block, 256 threads.
__global__ void k_out(const float* __restrict__ out_W, const float* __restrict__ out_b,
                      float* __restrict__ outp, int step) {
    __shared__ float lg[OUTD];
    int warp = threadIdx.x >> 5, lane = threadIdx.x & 31;
    const float* __restrict__ row = out_W + (size_t)warp * HID;
    float s = 0.f;
    for (int k = lane; k < HID; k += 32) s += row[k] * g_hdec[k];
    s = warp_red(s);
    if (!lane) lg[warp] = s + out_b[warp];
    __syncthreads();
    if (threadIdx.x == 0) {
        float mx = -1e30f;
        for (int i = 0; i < OUTD; i++) mx = fmaxf(mx, lg[i]);
        float sum = 0.f;
        for (int i = 0; i < OUTD; i++) sum += expf(lg[i] - mx);
        float lse = mx + logf(sum);
        for (int i = 0; i < OUTD; i++) {
            float lp = lg[i] - lse;
            outp[step * OUTD + i] = lp;
            g_u[i] = lp;
        }
    }
}

// ---------------- launch ----------------
extern "C" void kernel_launch(void* const* d_in, const int* in_sizes, int n_in,
                              void* d_out, int out_size) {
    const float* data     = (const float*)d_in[0];
    const float* enc_Wih  = (const float*)d_in[1];
    const float* enc_Whh  = (const float*)d_in[2];
    const float* enc_bih  = (const float*)d_in[3];
    const float* enc_bhh  = (const float*)d_in[4];
    const float* attn_W   = (const float*)d_in[5];
    const float* attn_b   = (const float*)d_in[6];
    const float* comb_W   = (const float*)d_in[7];
    const float* comb_b   = (const float*)d_in[8];
    const float* gru_Wih  = (const float*)d_in[9];
    const float* gru_Whh  = (const float*)d_in[10];
    const float* gru_bih  = (const float*)d_in[11];
    const float* gru_bhh  = (const float*)d_in[12];
    const float* out_W    = (const float*)d_in[13];
    const float* out_b    = (const float*)d_in[14];
    float* out = (float*)d_out;

    k_init<<<960, 256>>>(enc_bih, enc_bhh);

    dim3 grid(HID / BN, BATCH / BM);   // 32 x 5
    for (int t = 0; t < T_STEPS; t++)
        k_lstm_step<<<grid, 128>>>(data, enc_Whh, enc_Wih, t);

    k_hdec_init<<<4, 256>>>();

    for (int s = 0; s < NSTEPS; s++) {
        k_attn<<<1, 256>>>(attn_W, attn_b);
        k_comb<<<HID / 8, 256>>>(comb_W, comb_b);
        k_gru_mv<<<(6 * HID) / 8, 256>>>(gru_Wih, gru_Whh, gru_bih, gru_bhh);
        k_gate<<<HID / 256, 256>>>();
        k_out<<<1, 256>>>(out_W, out_b, out, s);
    }
}

// round 4
// speedup vs baseline: 3.8678x; 3.8678x over previous
#include <cuda_runtime.h>
#include <cuda_bf16.h>
#include <math.h>
#include <cstdint>

#define T_STEPS 240
#define BATCH   240
#define MPAD    256
#define INPUTD  256
#define HID     1024
#define NSTEPS  30
#define OUTD    8
#define WW      240
#define KTOT    1280
#define KCH     64
#define NCHUNK  (KTOT / KCH)   // 20

// smem buffer: Ah 16K | Al 16K | Bh 8K | Bl 8K = 48K, x3 buffers
#define BUFB   49152
#define SMEMB  (3 * BUFB)

// ---------------------------------------------------------------------------
// helpers
// ---------------------------------------------------------------------------
__device__ __forceinline__ uint32_t smem_to_u32(const void* p) {
    uint32_t a;
    asm("{ .reg .u64 t; cvta.to.shared.u64 t, %1; cvt.u32.u64 %0, t; }" : "=r"(a) : "l"(p));
    return a;
}

#define CP_ASYNC16(dst, src) \
    asm volatile("cp.async.cg.shared.global [%0], [%1], 16;" \
                 :: "r"(dst), "l"(__cvta_generic_to_global(src)))
#define CP_COMMIT() asm volatile("cp.async.commit_group;" ::: "memory")
#define CP_WAIT1()  asm volatile("cp.async.wait_group 1;" ::: "memory")
#define CP_WAIT0()  asm volatile("cp.async.wait_group 0;" ::: "memory")

#define LDSM4(r, addr) \
    asm volatile("ldmatrix.sync.aligned.m8n8.x4.shared.b16 {%0,%1,%2,%3}, [%4];" \
                 : "=r"((r)[0]), "=r"((r)[1]), "=r"((r)[2]), "=r"((r)[3]) : "r"(addr))

#define MMA16816(d, a, b) \
    asm volatile("mma.sync.aligned.m16n8k16.row.col.f32.bf16.bf16.f32 " \
                 "{%0,%1,%2,%3}, {%4,%5,%6,%7}, {%8,%9}, {%0,%1,%2,%3};" \
                 : "+f"((d)[0]), "+f"((d)[1]), "+f"((d)[2]), "+f"((d)[3]) \
                 : "r"((a)[0]), "r"((a)[1]), "r"((a)[2]), "r"((a)[3]), \
                   "r"((b)[0]), "r"((b)[1]))

// ---------------------------------------------------------------------------
// device scratch (no allocations allowed)
// ---------------------------------------------------------------------------
__device__ __align__(256) __nv_bfloat16 g_W_hi[4096 * KTOT];
__device__ __align__(256) __nv_bfloat16 g_W_lo[4096 * KTOT];
__device__ __align__(256) __nv_bfloat16 g_x_hi[(size_t)T_STEPS * MPAD * INPUTD];
__device__ __align__(256) __nv_bfloat16 g_x_lo[(size_t)T_STEPS * MPAD * INPUTD];
__device__ __align__(256) __nv_bfloat16 g_hA_hi[2][MPAD * HID];
__device__ __align__(256) __nv_bfloat16 g_hA_lo[2][MPAD * HID];
__device__ float g_c[MPAD * HID];
__device__ float g_bias[4 * HID];

__device__ float g_u[OUTD];
__device__ float g_hdec[HID];
__device__ float g_applied[HID];
__device__ float g_comb[HID];
__device__ float g_gi[3 * HID];
__device__ float g_gh[3 * HID];

__device__ __forceinline__ float sigf(float x) { return 1.f / (1.f + expf(-x)); }
__device__ __forceinline__ float warp_red(float s) {
#pragma unroll
    for (int o = 16; o; o >>= 1) s += __shfl_down_sync(0xffffffffu, s, o);
    return s;
}

// ---------------------------------------------------------------------------
// init / convert
// ---------------------------------------------------------------------------
__global__ void k_init(const float* __restrict__ bih, const float* __restrict__ bhh) {
    int i = blockIdx.x * blockDim.x + threadIdx.x;
    int n = MPAD * HID;
    __nv_bfloat16 z = __float2bfloat16(0.f);
    for (int j = i; j < n; j += gridDim.x * blockDim.x) {
        g_c[j] = 0.f;
        g_hA_hi[0][j] = z; g_hA_hi[1][j] = z;
        g_hA_lo[0][j] = z; g_hA_lo[1][j] = z;
    }
    if (i < 4 * HID) g_bias[i] = bih[i] + bhh[i];
}

__global__ void k_conv_w(const float* __restrict__ Whh, const float* __restrict__ Wih) {
    size_t i = (size_t)blockIdx.x * blockDim.x + threadIdx.x;
    if (i >= (size_t)4096 * KTOT) return;
    int r = (int)(i / KTOT);
    int k = (int)(i % KTOT);
    float v = (k < HID) ? Whh[(size_t)r * HID + k] : Wih[(size_t)r * INPUTD + (k - HID)];
    __nv_bfloat16 hi = __float2bfloat16(v);
    g_W_hi[i] = hi;
    g_W_lo[i] = __float2bfloat16(v - __bfloat162float(hi));
}

__global__ void k_conv_x(const float* __restrict__ data) {
    size_t i = (size_t)blockIdx.x * blockDim.x + threadIdx.x;
    if (i >= (size_t)T_STEPS * MPAD * INPUTD) return;
    int k = (int)(i % INPUTD);
    int b = (int)((i / INPUTD) % MPAD);
    int t = (int)(i / ((size_t)MPAD * INPUTD));
    float v = (b < BATCH) ? data[((size_t)t * BATCH + b) * INPUTD + k] : 0.f;
    __nv_bfloat16 hi = __float2bfloat16(v);
    g_x_hi[i] = hi;
    g_x_lo[i] = __float2bfloat16(v - __bfloat162float(hi));
}

// ---------------------------------------------------------------------------
// mma.sync LSTM step.
// grid (64, 2): bx -> 16 hid cols (x4 gates => BN=64 weight rows), by -> 128 m rows
// 256 threads = 8 warps: wr = wid&3 (m, 32 rows), wc = wid>>2 (hid, 8 cols)
// warp n-tiles = 4 gates (8 cols each) -> all gates of an (m,hid) cell in-lane.
// ---------------------------------------------------------------------------
__global__ __launch_bounds__(256, 1) void k_step(int t) {
    extern __shared__ __align__(128) char smem[];
    const uint32_t sb = smem_to_u32(smem);
    const int tid  = threadIdx.x;
    const int lane = tid & 31;
    const int wid  = tid >> 5;
    const int wr   = wid & 3;
    const int wc   = wid >> 2;
    const int n0   = blockIdx.x * 16;   // hid col base
    const int m0   = blockIdx.y * 128;
    const int par  = t & 1;

    const __nv_bfloat16* __restrict__ hHi = g_hA_hi[par];
    const __nv_bfloat16* __restrict__ hLo = g_hA_lo[par];
    const __nv_bfloat16* __restrict__ xHi = g_x_hi + (size_t)t * MPAD * INPUTD;
    const __nv_bfloat16* __restrict__ xLo = g_x_lo + (size_t)t * MPAD * INPUTD;

    auto load_chunk = [&](int c) {
        const uint32_t base = sb + (c % 3) * BUFB;
        const int k0 = c * KCH;
        const __nv_bfloat16 *ah, *al;
        int astr, ak;
        if (k0 < HID) { ah = hHi; al = hLo; astr = HID;    ak = k0; }
        else          { ah = xHi; al = xLo; astr = INPUTD; ak = k0 - HID; }
        // A: 128 rows x 64 k, hi + lo
#pragma unroll
        for (int i = tid; i < 1024; i += 256) {
            int r = i >> 3, ch = i & 7;
            uint32_t dst = base + r * 128 + (((uint32_t)(ch ^ (r & 7))) << 4);
            size_t off = (size_t)(m0 + r) * astr + ak + ch * 8;
            CP_ASYNC16(dst,         ah + off);
            CP_ASYNC16(dst + 16384, al + off);
        }
        // B: 64 weight rows (gate*16 + hidlocal) x 64 k, hi + lo
#pragma unroll
        for (int i = tid; i < 512; i += 256) {
            int r = i >> 3, ch = i & 7;
            uint32_t dst = base + 32768 + r * 128 + (((uint32_t)(ch ^ (r & 7))) << 4);
            int wrow = (r >> 4) * HID + n0 + (r & 15);
            size_t off = (size_t)wrow * KTOT + k0 + ch * 8;
            CP_ASYNC16(dst,        g_W_hi + off);
            CP_ASYNC16(dst + 8192, g_W_lo + off);
        }
        CP_COMMIT();
    };

    float acc[2][4][4];
#pragma unroll
    for (int mt = 0; mt < 2; mt++)
#pragma unroll
        for (int q = 0; q < 4; q++)
#pragma unroll
            for (int j = 0; j < 4; j++) acc[mt][q][j] = 0.f;

    load_chunk(0);
    load_chunk(1);

    for (int c = 0; c < NCHUNK; c++) {
        if (c == NCHUNK - 1) { CP_WAIT0(); } else { CP_WAIT1(); }
        __syncthreads();
        if (c + 2 < NCHUNK) load_chunk(c + 2);

        const uint32_t base = sb + (c % 3) * BUFB;
        const uint32_t Ah = base, Al = base + 16384, Bh = base + 32768, Bl = base + 40960;

#pragma unroll
        for (int ks = 0; ks < 4; ks++) {
            uint32_t ahf[2][4], alf[2][4], bhf[4][2], blf[4][2];
#pragma unroll
            for (int mt = 0; mt < 2; mt++) {
                int r = wr * 32 + mt * 16 + (lane & 15);
                uint32_t ch = ((uint32_t)((ks * 2 + (lane >> 4)) ^ (r & 7))) << 4;
                LDSM4(ahf[mt], Ah + r * 128 + ch);
                LDSM4(alf[mt], Al + r * 128 + ch);
            }
#pragma unroll
            for (int gp = 0; gp < 2; gp++) {
                int rn = (gp * 2 + (lane >> 4)) * 16 + wc * 8 + (lane & 7);
                uint32_t ch = ((uint32_t)((ks * 2 + ((lane >> 3) & 1)) ^ (rn & 7))) << 4;
                uint32_t* bp = &bhf[gp * 2][0];
                LDSM4(bp, Bh + rn * 128 + ch);
                uint32_t* bp2 = &blf[gp * 2][0];
                LDSM4(bp2, Bl + rn * 128 + ch);
            }
#pragma unroll
            for (int mt = 0; mt < 2; mt++)
#pragma unroll
                for (int q = 0; q < 4; q++) {
                    MMA16816(acc[mt][q], ahf[mt], bhf[q]);
                    MMA16816(acc[mt][q], ahf[mt], blf[q]);
                    MMA16816(acc[mt][q], alf[mt], bhf[q]);
                }
        }
    }

    // fused LSTM gate epilogue (all 4 gates in-lane)
    __nv_bfloat16* __restrict__ oHi = g_hA_hi[par ^ 1];
    __nv_bfloat16* __restrict__ oLo = g_hA_lo[par ^ 1];
    const int rowq = lane >> 2;
    const int col2 = (lane & 3) * 2;
#pragma unroll
    for (int mt = 0; mt < 2; mt++) {
#pragma unroll
        for (int rsl = 0; rsl < 4; rsl++) {
            int m = m0 + wr * 32 + mt * 16 + rowq + ((rsl & 2) ? 8 : 0);
            if (m >= BATCH) continue;
            int n = n0 + wc * 8 + col2 + (rsl & 1);
            float gi = acc[mt][0][rsl] + g_bias[n];
            float gf = acc[mt][1][rsl] + g_bias[HID + n];
            float gg = acc[mt][2][rsl] + g_bias[2 * HID + n];
            float go = acc[mt][3][rsl] + g_bias[3 * HID + n];
            size_t idx = (size_t)m * HID + n;
            float cn = sigf(gf) * g_c[idx] + sigf(gi) * tanhf(gg);
            g_c[idx] = cn;
            float h = sigf(go) * tanhf(cn);
            __nv_bfloat16 hh = __float2bfloat16(h);
            oHi[idx] = hh;
            oLo[idx] = __float2bfloat16(h - __bfloat162float(hh));
        }
    }
}

// ---------------------------------------------------------------------------
// decoder (batch-1, L2-resident matvecs)
// ---------------------------------------------------------------------------
__device__ __forceinline__ float ctx_at(size_t idx) {
    return __bfloat162float(g_hA_hi[0][idx]) + __bfloat162float(g_hA_lo[0][idx]);
}

__global__ void k_hdec_init() {
    int i = blockIdx.x * blockDim.x + threadIdx.x;
    if (i < HID) g_hdec[i] = ctx_at((size_t)(BATCH - 1) * HID + i);
    if (i < OUTD) g_u[i] = 1.f / OUTD;
}

__global__ void k_attn(const float* __restrict__ attn_W, const float* __restrict__ attn_b) {
    __shared__ float v[HID + OUTD];
    __shared__ float sc[WW];
    __shared__ float sinv;
    const int tid = threadIdx.x;

    for (int i = tid; i < OUTD; i += 256) v[i] = g_u[i];
    for (int i = tid; i < HID; i += 256) v[OUTD + i] = g_hdec[i];
    __syncthreads();

    const int warp = tid >> 5, lane = tid & 31;
    for (int j = warp; j < WW; j += 8) {
        const float* __restrict__ row = attn_W + (size_t)j * (HID + OUTD);
        float s = 0.f;
        for (int k = lane; k < HID + OUTD; k += 32) s += row[k] * v[k];
        s = warp_red(s);
        if (!lane) sc[j] = s + attn_b[j];
    }
    __syncthreads();
    if (tid == 0) {
        float mx = -1e30f;
        for (int j = 0; j < WW; j++) mx = fmaxf(mx, sc[j]);
        float sum = 0.f;
        for (int j = 0; j < WW; j++) { float e = expf(sc[j] - mx); sc[j] = e; sum += e; }
        sinv = 1.f / sum;
    }
    __syncthreads();
    const float inv = sinv;
    for (int n = tid; n < HID; n += 256) {
        float s = 0.f;
        for (int j = 0; j < WW; j++) s += sc[j] * ctx_at((size_t)j * HID + n);
        g_applied[n] = s * inv;
    }
}

__global__ void k_comb(const float* __restrict__ comb_W, const float* __restrict__ comb_b) {
    int warp = (blockIdx.x * blockDim.x + threadIdx.x) >> 5;
    int lane = threadIdx.x & 31;
    if (warp >= HID) return;
    const float* __restrict__ row = comb_W + (size_t)warp * (HID + OUTD);
    float s = 0.f;
    if (lane < OUTD) s += row[lane] * g_u[lane];
    for (int k = lane; k < HID; k += 32) s += row[OUTD + k] * g_applied[k];
    s = warp_red(s);
    if (!lane) g_comb[warp] = fmaxf(s + comb_b[warp], 0.f);
}

__global__ void k_gru_mv(const float* __restrict__ Wih, const float* __restrict__ Whh,
                         const float* __restrict__ bih, const float* __restrict__ bhh) {
    int warp = (blockIdx.x * blockDim.x + threadIdx.x) >> 5;
    int lane = threadIdx.x & 31;
    if (warp < 3 * HID) {
        const float* __restrict__ row = Wih + (size_t)warp * HID;
        float s = 0.f;
        for (int k = lane; k < HID; k += 32) s += row[k] * g_comb[k];
        s = warp_red(s);
        if (!lane) g_gi[warp] = s + bih[warp];
    } else {
        int r = warp - 3 * HID;
        const float* __restrict__ row = Whh + (size_t)r * HID;
        float s = 0.f;
        for (int k = lane; k < HID; k += 32) s += row[k] * g_hdec[k];
        s = warp_red(s);
        if (!lane) g_gh[r] = s + bhh[r];
    }
}

__global__ void k_gate() {
    int n = blockIdx.x * blockDim.x + threadIdx.x;
    if (n >= HID) return;
    float r  = sigf(g_gi[n] + g_gh[n]);
    float z  = sigf(g_gi[HID + n] + g_gh[HID + n]);
    float nn = tanhf(g_gi[2 * HID + n] + r * g_gh[2 * HID + n]);
    g_hdec[n] = (1.f - z) * nn + z * g_hdec[n];
}

__global__ void k_out(const float* __restrict__ out_W, const float* __restrict__ out_b,
                      float* __restrict__ outp, int step) {
    __shared__ float lg[OUTD];
    int warp = threadIdx.x >> 5, lane = threadIdx.x & 31;
    const float* __restrict__ row = out_W + (size_t)warp * HID;
    float s = 0.f;
    for (int k = lane; k < HID; k += 32) s += row[k] * g_hdec[k];
    s = warp_red(s);
    if (!lane) lg[warp] = s + out_b[warp];
    __syncthreads();
    if (threadIdx.x == 0) {
        float mx = -1e30f;
        for (int i = 0; i < OUTD; i++) mx = fmaxf(mx, lg[i]);
        float sum = 0.f;
        for (int i = 0; i < OUTD; i++) sum += expf(lg[i] - mx);
        float lse = mx + logf(sum);
        for (int i = 0; i < OUTD; i++) {
            float lp = lg[i] - lse;
            outp[step * OUTD + i] = lp;
            g_u[i] = lp;
        }
    }
}

// ---------------------------------------------------------------------------
// launch
// ---------------------------------------------------------------------------
extern "C" void kernel_launch(void* const* d_in, const int* in_sizes, int n_in,
                              void* d_out, int out_size) {
    const float* data     = (const float*)d_in[0];
    const float* enc_Wih  = (const float*)d_in[1];
    const float* enc_Whh  = (const float*)d_in[2];
    const float* enc_bih  = (const float*)d_in[3];
    const float* enc_bhh  = (const float*)d_in[4];
    const float* attn_W   = (const float*)d_in[5];
    const float* attn_b   = (const float*)d_in[6];
    const float* comb_W   = (const float*)d_in[7];
    const float* comb_b   = (const float*)d_in[8];
    const float* gru_Wih  = (const float*)d_in[9];
    const float* gru_Whh  = (const float*)d_in[10];
    const float* gru_bih  = (const float*)d_in[11];
    const float* gru_bhh  = (const float*)d_in[12];
    const float* out_W    = (const float*)d_in[13];
    const float* out_b    = (const float*)d_in[14];
    float* out = (float*)d_out;

    static int smem_set = 0;
    if (!smem_set) {
        cudaFuncSetAttribute(k_step, cudaFuncAttributeMaxDynamicSharedMemorySize, SMEMB);
        smem_set = 1;
    }

    k_init<<<1024, 256>>>(enc_bih, enc_bhh);
    k_conv_w<<<(4096 * KTOT + 255) / 256, 256>>>(enc_Whh, enc_Wih);
    k_conv_x<<<(T_STEPS * MPAD * INPUTD + 255) / 256, 256>>>(data);

    dim3 grid(HID / 16, 2);   // 64 x 2 = 128 CTAs
    for (int t = 0; t < T_STEPS; t++)
        k_step<<<grid, 256, SMEMB>>>(t);

    k_hdec_init<<<4, 256>>>();

    for (int s = 0; s < NSTEPS; s++) {
        k_attn<<<1, 256>>>(attn_W, attn_b);
        k_comb<<<HID / 8, 256>>>(comb_W, comb_b);
        k_gru_mv<<<(6 * HID) / 8, 256>>>(gru_Wih, gru_Whh, gru_bih, gru_bhh);
        k_gate<<<HID / 256, 256>>>();
        k_out<<<1, 256>>>(out_W, out_b, out, s);
    }
}

// round 5
// speedup vs baseline: 4.1579x; 1.0750x over previous
#include <cuda_runtime.h>
#include <cuda_bf16.h>
#include <math.h>
#include <cstdint>

#define T_STEPS 240
#define BATCH   240
#define MPAD    256
#define INPUTD  256
#define HID     1024
#define NSTEPS  30
#define OUTD    8
#define WW      240
#define KTOT    1280
#define KCH     64
#define NCHUNK  (KTOT / KCH)   // 20

#define NCTA_ENC 128
#define NCTA_DEC 32

// smem buffer: Ah 16K | Al 16K | Bh 8K | Bl 8K = 48K, x3 buffers
#define BUFB   49152
#define SMEMB  (3 * BUFB)

// ---------------------------------------------------------------------------
// helpers
// ---------------------------------------------------------------------------
__device__ __forceinline__ uint32_t smem_to_u32(const void* p) {
    uint32_t a;
    asm("{ .reg .u64 t; cvta.to.shared.u64 t, %1; cvt.u32.u64 %0, t; }" : "=r"(a) : "l"(p));
    return a;
}

#define CP_ASYNC16(dst, src) \
    asm volatile("cp.async.cg.shared.global [%0], [%1], 16;" \
                 :: "r"(dst), "l"(__cvta_generic_to_global(src)))
#define CP_COMMIT() asm volatile("cp.async.commit_group;" ::: "memory")
#define CP_WAIT1()  asm volatile("cp.async.wait_group 1;" ::: "memory")
#define CP_WAIT0()  asm volatile("cp.async.wait_group 0;" ::: "memory")

#define LDSM4(r, addr) \
    asm volatile("ldmatrix.sync.aligned.m8n8.x4.shared.b16 {%0,%1,%2,%3}, [%4];" \
                 : "=r"((r)[0]), "=r"((r)[1]), "=r"((r)[2]), "=r"((r)[3]) : "r"(addr))

#define MMA16816(d, a, b) \
    asm volatile("mma.sync.aligned.m16n8k16.row.col.f32.bf16.bf16.f32 " \
                 "{%0,%1,%2,%3}, {%4,%5,%6,%7}, {%8,%9}, {%0,%1,%2,%3};" \
                 : "+f"((d)[0]), "+f"((d)[1]), "+f"((d)[2]), "+f"((d)[3]) \
                 : "r"((a)[0]), "r"((a)[1]), "r"((a)[2]), "r"((a)[3]), \
                   "r"((b)[0]), "r"((b)[1]))

// ---------------------------------------------------------------------------
// device scratch (no allocations allowed)
// ---------------------------------------------------------------------------
__device__ __align__(256) __nv_bfloat16 g_W_hi[4096 * KTOT];
__device__ __align__(256) __nv_bfloat16 g_W_lo[4096 * KTOT];
__device__ __align__(256) __nv_bfloat16 g_x_hi[(size_t)T_STEPS * MPAD * INPUTD];
__device__ __align__(256) __nv_bfloat16 g_x_lo[(size_t)T_STEPS * MPAD * INPUTD];
__device__ __align__(256) __nv_bfloat16 g_hA_hi[2][MPAD * HID];
__device__ __align__(256) __nv_bfloat16 g_hA_lo[2][MPAD * HID];
__device__ float g_c[MPAD * HID];
__device__ float g_bias[4 * HID];

__device__ float g_u[OUTD];
__device__ float g_hdec[HID];
__device__ float g_applied[HID];
__device__ float g_comb[HID];
__device__ float g_gi[3 * HID];
__device__ float g_gh[3 * HID];
__device__ float g_sc[WW];
__device__ float g_aw[WW];

// grid barrier state
__device__ unsigned g_bcnt = 0;
__device__ volatile unsigned g_bgen = 0;

__device__ __forceinline__ void gbar(unsigned nctas) {
    __syncthreads();
    if (threadIdx.x == 0) {
        __threadfence();
        unsigned gen = g_bgen;
        if (atomicAdd(&g_bcnt, 1u) == nctas - 1u) {
            g_bcnt = 0;
            __threadfence();
            g_bgen = gen + 1u;
        } else {
            while (g_bgen == gen) __nanosleep(32);
        }
        __threadfence();
    }
    __syncthreads();
}

__device__ __forceinline__ float sigf(float x) { return 1.f / (1.f + expf(-x)); }
__device__ __forceinline__ float warp_red(float s) {
#pragma unroll
    for (int o = 16; o; o >>= 1) s += __shfl_down_sync(0xffffffffu, s, o);
    return s;
}
__device__ __forceinline__ float ctx_at(size_t idx) {
    return __bfloat162float(g_hA_hi[0][idx]) + __bfloat162float(g_hA_lo[0][idx]);
}

// ---------------------------------------------------------------------------
// init / convert
// ---------------------------------------------------------------------------
__global__ void k_init(const float* __restrict__ bih, const float* __restrict__ bhh) {
    int i = blockIdx.x * blockDim.x + threadIdx.x;
    int n = MPAD * HID;
    __nv_bfloat16 z = __float2bfloat16(0.f);
    for (int j = i; j < n; j += gridDim.x * blockDim.x) {
        g_c[j] = 0.f;
        g_hA_hi[0][j] = z; g_hA_hi[1][j] = z;
        g_hA_lo[0][j] = z; g_hA_lo[1][j] = z;
    }
    if (i < 4 * HID) g_bias[i] = bih[i] + bhh[i];
}

__global__ void k_conv_w(const float* __restrict__ Whh, const float* __restrict__ Wih) {
    size_t i = (size_t)blockIdx.x * blockDim.x + threadIdx.x;
    if (i >= (size_t)4096 * KTOT) return;
    int r = (int)(i / KTOT);
    int k = (int)(i % KTOT);
    float v = (k < HID) ? Whh[(size_t)r * HID + k] : Wih[(size_t)r * INPUTD + (k - HID)];
    __nv_bfloat16 hi = __float2bfloat16(v);
    g_W_hi[i] = hi;
    g_W_lo[i] = __float2bfloat16(v - __bfloat162float(hi));
}

__global__ void k_conv_x(const float* __restrict__ data) {
    size_t i = (size_t)blockIdx.x * blockDim.x + threadIdx.x;
    if (i >= (size_t)T_STEPS * MPAD * INPUTD) return;
    int k = (int)(i % INPUTD);
    int b = (int)((i / INPUTD) % MPAD);
    int t = (int)(i / ((size_t)MPAD * INPUTD));
    float v = (b < BATCH) ? data[((size_t)t * BATCH + b) * INPUTD + k] : 0.f;
    __nv_bfloat16 hi = __float2bfloat16(v);
    g_x_hi[i] = hi;
    g_x_lo[i] = __float2bfloat16(v - __bfloat162float(hi));
}

// ---------------------------------------------------------------------------
// persistent encoder: all 240 LSTM steps in one kernel.
// 128 CTAs x 512 threads (16 warps). CTA tile: 128 m x 16 hid (x4 gates).
// warp: wr = wid&7 -> 16 m rows; wc = wid>>3 -> 8 hid cols (x4 gate n-tiles).
// ---------------------------------------------------------------------------
__global__ __launch_bounds__(512, 1) void k_enc() {
    extern __shared__ __align__(128) char smem[];
    const uint32_t sb = smem_to_u32(smem);
    const int tid  = threadIdx.x;
    const int lane = tid & 31;
    const int wid  = tid >> 5;
    const int wr   = wid & 7;
    const int wc   = wid >> 3;
    const int n0   = (blockIdx.x & 63) * 16;
    const int m0   = (blockIdx.x >> 6) * 128;

    for (int t = 0; t < T_STEPS; t++) {
        const int par = t & 1;
        const __nv_bfloat16* __restrict__ hHi = g_hA_hi[par];
        const __nv_bfloat16* __restrict__ hLo = g_hA_lo[par];
        const __nv_bfloat16* __restrict__ xHi = g_x_hi + (size_t)t * MPAD * INPUTD;
        const __nv_bfloat16* __restrict__ xLo = g_x_lo + (size_t)t * MPAD * INPUTD;

        auto load_chunk = [&](int c) {
            const uint32_t base = sb + (c % 3) * BUFB;
            const int k0 = c * KCH;
            const __nv_bfloat16 *ah, *al;
            int astr, ak;
            if (k0 < HID) { ah = hHi; al = hLo; astr = HID;    ak = k0; }
            else          { ah = xHi; al = xLo; astr = INPUTD; ak = k0 - HID; }
            // A: 128 rows x 64 k, hi + lo
#pragma unroll
            for (int i = tid; i < 1024; i += 512) {
                int r = i >> 3, ch = i & 7;
                uint32_t dst = base + r * 128 + (((uint32_t)(ch ^ (r & 7))) << 4);
                size_t off = (size_t)(m0 + r) * astr + ak + ch * 8;
                CP_ASYNC16(dst,         ah + off);
                CP_ASYNC16(dst + 16384, al + off);
            }
            // B: 64 weight rows (gate*16 + hidlocal) x 64 k, hi + lo
            {
                int i = tid;
                if (i < 512) {
                    int r = i >> 3, ch = i & 7;
                    uint32_t dst = base + 32768 + r * 128 + (((uint32_t)(ch ^ (r & 7))) << 4);
                    int wrow = (r >> 4) * HID + n0 + (r & 15);
                    size_t off = (size_t)wrow * KTOT + (size_t)c * KCH + ch * 8;
                    CP_ASYNC16(dst,        g_W_hi + off);
                    CP_ASYNC16(dst + 8192, g_W_lo + off);
                }
            }
            CP_COMMIT();
        };

        float acc[4][4];
#pragma unroll
        for (int q = 0; q < 4; q++)
#pragma unroll
            for (int j = 0; j < 4; j++) acc[q][j] = 0.f;

        load_chunk(0);
        load_chunk(1);

        for (int c = 0; c < NCHUNK; c++) {
            if (c == NCHUNK - 1) { CP_WAIT0(); } else { CP_WAIT1(); }
            __syncthreads();
            if (c + 2 < NCHUNK) load_chunk(c + 2);

            const uint32_t base = sb + (c % 3) * BUFB;
            const uint32_t Ah = base, Al = base + 16384, Bh = base + 32768, Bl = base + 40960;

#pragma unroll
            for (int ks = 0; ks < 4; ks++) {
                uint32_t ahf[4], alf[4], bhf[4][2], blf[4][2];
                {
                    int r = wr * 16 + (lane & 15);
                    uint32_t ch = ((uint32_t)((ks * 2 + (lane >> 4)) ^ (r & 7))) << 4;
                    LDSM4(ahf, Ah + r * 128 + ch);
                    LDSM4(alf, Al + r * 128 + ch);
                }
#pragma unroll
                for (int gp = 0; gp < 2; gp++) {
                    int rn = (gp * 2 + (lane >> 4)) * 16 + wc * 8 + (lane & 7);
                    uint32_t ch = ((uint32_t)((ks * 2 + ((lane >> 3) & 1)) ^ (rn & 7))) << 4;
                    LDSM4(&bhf[gp * 2][0], Bh + rn * 128 + ch);
                    LDSM4(&blf[gp * 2][0], Bl + rn * 128 + ch);
                }
#pragma unroll
                for (int q = 0; q < 4; q++) {
                    MMA16816(acc[q], ahf, bhf[q]);
                    MMA16816(acc[q], ahf, blf[q]);
                    MMA16816(acc[q], alf, bhf[q]);
                }
            }
        }

        // fused LSTM gate epilogue (all 4 gates in-lane), 4 cells per thread
        __nv_bfloat16* __restrict__ oHi = g_hA_hi[par ^ 1];
        __nv_bfloat16* __restrict__ oLo = g_hA_lo[par ^ 1];
        const int rowq = lane >> 2;
        const int col2 = (lane & 3) * 2;
#pragma unroll
        for (int rsl = 0; rsl < 4; rsl++) {
            int m = m0 + wr * 16 + rowq + ((rsl & 2) ? 8 : 0);
            int n = n0 + wc * 8 + col2 + (rsl & 1);
            if (m < BATCH) {
                float gi = acc[0][rsl] + g_bias[n];
                float gf = acc[1][rsl] + g_bias[HID + n];
                float gg = acc[2][rsl] + g_bias[2 * HID + n];
                float go = acc[3][rsl] + g_bias[3 * HID + n];
                size_t idx = (size_t)m * HID + n;
                float cn = sigf(gf) * g_c[idx] + sigf(gi) * tanhf(gg);
                g_c[idx] = cn;
                float h = sigf(go) * tanhf(cn);
                __nv_bfloat16 hh = __float2bfloat16(h);
                oHi[idx] = hh;
                oLo[idx] = __float2bfloat16(h - __bfloat162float(hh));
            }
        }

        gbar(NCTA_ENC);
    }
}

// ---------------------------------------------------------------------------
// persistent decoder: all 30 GRU/attention steps. 32 CTAs x 256 threads.
// ---------------------------------------------------------------------------
__global__ __launch_bounds__(256, 1) void k_dec(
    const float* __restrict__ attn_W, const float* __restrict__ attn_b,
    const float* __restrict__ comb_W, const float* __restrict__ comb_b,
    const float* __restrict__ gWih,   const float* __restrict__ gWhh,
    const float* __restrict__ gbih,   const float* __restrict__ gbhh,
    const float* __restrict__ out_W,  const float* __restrict__ out_b,
    float* __restrict__ outp)
{
    const int tid  = threadIdx.x;
    const int bid  = blockIdx.x;
    const int lane = tid & 31;
    const int gw   = bid * 8 + (tid >> 5);
    const int gt   = bid * 256 + tid;

    // init hdec, u
    if (gt < HID) g_hdec[gt] = ctx_at((size_t)(BATCH - 1) * HID + gt);
    if (gt < OUTD) g_u[gt] = 1.f / OUTD;
    gbar(NCTA_DEC);

    for (int step = 0; step < NSTEPS; step++) {
        // ---- attention scores (240 warps) ----
        if (gw < WW) {
            const float* __restrict__ row = attn_W + (size_t)gw * (HID + OUTD);
            float s = 0.f;
            for (int k = lane; k < HID + OUTD; k += 32) {
                float v = (k < OUTD) ? g_u[k] : g_hdec[k - OUTD];
                s += row[k] * v;
            }
            s = warp_red(s);
            if (!lane) g_sc[gw] = s + attn_b[gw];
        }
        gbar(NCTA_DEC);

        // ---- softmax (CTA 0) ----
        if (bid == 0) {
            __shared__ float rbuf[8];
            float x = (tid < WW) ? g_sc[tid] : -1e30f;
            float mx = x;
#pragma unroll
            for (int o = 16; o; o >>= 1) mx = fmaxf(mx, __shfl_xor_sync(0xffffffffu, mx, o));
            if (!lane) rbuf[tid >> 5] = mx;
            __syncthreads();
            float bm = rbuf[0];
#pragma unroll
            for (int i = 1; i < 8; i++) bm = fmaxf(bm, rbuf[i]);
            float e = (tid < WW) ? expf(x - bm) : 0.f;
            float sm = e;
#pragma unroll
            for (int o = 16; o; o >>= 1) sm += __shfl_xor_sync(0xffffffffu, sm, o);
            __syncthreads();
            if (!lane) rbuf[tid >> 5] = sm;
            __syncthreads();
            float tot = 0.f;
#pragma unroll
            for (int i = 0; i < 8; i++) tot += rbuf[i];
            if (tid < WW) g_aw[tid] = e / tot;
        }
        gbar(NCTA_DEC);

        // ---- applied = aw @ ctx (1024 cols over 256 warps) ----
        for (int n = gw; n < HID; n += 256) {
            float s = 0.f;
            for (int j = lane; j < WW; j += 32) s += g_aw[j] * ctx_at((size_t)j * HID + n);
            s = warp_red(s);
            if (!lane) g_applied[n] = s;
        }
        gbar(NCTA_DEC);

        // ---- comb = relu(comb_W @ [u; applied] + b) ----
        for (int r = gw; r < HID; r += 256) {
            const float* __restrict__ row = comb_W + (size_t)r * (HID + OUTD);
            float s = 0.f;
            for (int k = lane; k < HID + OUTD; k += 32) {
                float v = (k < OUTD) ? g_u[k] : g_applied[k - OUTD];
                s += row[k] * v;
            }
            s = warp_red(s);
            if (!lane) g_comb[r] = fmaxf(s + comb_b[r], 0.f);
        }
        gbar(NCTA_DEC);

        // ---- gi / gh (6144 rows) ----
        for (int r = gw; r < 6 * HID; r += 256) {
            if (r < 3 * HID) {
                const float* __restrict__ row = gWih + (size_t)r * HID;
                float s = 0.f;
                for (int k = lane; k < HID; k += 32) s += row[k] * g_comb[k];
                s = warp_red(s);
                if (!lane) g_gi[r] = s + gbih[r];
            } else {
                int rr = r - 3 * HID;
                const float* __restrict__ row = gWhh + (size_t)rr * HID;
                float s = 0.f;
                for (int k = lane; k < HID; k += 32) s += row[k] * g_hdec[k];
                s = warp_red(s);
                if (!lane) g_gh[rr] = s + gbhh[rr];
            }
        }
        gbar(NCTA_DEC);

        // ---- gate update + output head (CTA 0) ----
        if (bid == 0) {
            for (int n = tid; n < HID; n += 256) {
                float r  = sigf(g_gi[n] + g_gh[n]);
                float z  = sigf(g_gi[HID + n] + g_gh[HID + n]);
                float nn = tanhf(g_gi[2 * HID + n] + r * g_gh[2 * HID + n]);
                g_hdec[n] = (1.f - z) * nn + z * g_hdec[n];
            }
            __syncthreads();
            __shared__ float lg[OUTD];
            int w = tid >> 5;
            if (w < OUTD) {
                const float* __restrict__ row = out_W + (size_t)w * HID;
                float s = 0.f;
                for (int k = lane; k < HID; k += 32) s += row[k] * g_hdec[k];
                s = warp_red(s);
                if (!lane) lg[w] = s + out_b[w];
            }
            __syncthreads();
            if (tid == 0) {
                float mx = -1e30f;
#pragma unroll
                for (int i = 0; i < OUTD; i++) mx = fmaxf(mx, lg[i]);
                float sum = 0.f;
#pragma unroll
                for (int i = 0; i < OUTD; i++) sum += expf(lg[i] - mx);
                float lse = mx + logf(sum);
#pragma unroll
                for (int i = 0; i < OUTD; i++) {
                    float lp = lg[i] - lse;
                    outp[step * OUTD + i] = lp;
                    g_u[i] = lp;
                }
            }
        }
        gbar(NCTA_DEC);
    }
}

// ---------------------------------------------------------------------------
// launch
// ---------------------------------------------------------------------------
extern "C" void kernel_launch(void* const* d_in, const int* in_sizes, int n_in,
                              void* d_out, int out_size) {
    const float* data     = (const float*)d_in[0];
    const float* enc_Wih  = (const float*)d_in[1];
    const float* enc_Whh  = (const float*)d_in[2];
    const float* enc_bih  = (const float*)d_in[3];
    const float* enc_bhh  = (const float*)d_in[4];
    const float* attn_W   = (const float*)d_in[5];
    const float* attn_b   = (const float*)d_in[6];
    const float* comb_W   = (const float*)d_in[7];
    const float* comb_b   = (const float*)d_in[8];
    const float* gru_Wih  = (const float*)d_in[9];
    const float* gru_Whh  = (const float*)d_in[10];
    const float* gru_bih  = (const float*)d_in[11];
    const float* gru_bhh  = (const float*)d_in[12];
    const float* out_W    = (const float*)d_in[13];
    const float* out_b    = (const float*)d_in[14];
    float* out = (float*)d_out;

    cudaFuncSetAttribute(k_enc, cudaFuncAttributeMaxDynamicSharedMemorySize, SMEMB);

    k_init<<<1024, 256>>>(enc_bih, enc_bhh);
    k_conv_w<<<(4096 * KTOT + 255) / 256, 256>>>(enc_Whh, enc_Wih);
    k_conv_x<<<(T_STEPS * MPAD * INPUTD + 255) / 256, 256>>>(data);

    k_enc<<<NCTA_ENC, 512, SMEMB>>>();

    k_dec<<<NCTA_DEC, 256>>>(attn_W, attn_b, comb_W, comb_b,
                             gru_Wih, gru_Whh, gru_bih, gru_bhh,
                             out_W, out_b, out);
}

// round 6
// speedup vs baseline: 5.3247x; 1.2806x over previous
#include <cuda_runtime.h>
#include <cuda_bf16.h>
#include <math.h>
#include <cstdint>

#define T_STEPS 240
#define BATCH   240
#define MPAD    256
#define INPUTD  256
#define HID     1024
#define NSTEPS  30
#define OUTD    8
#define WW      240
#define KTOT    1280
#define KCH     64
#define NCH_H   16          // serial chunks (K=1024, h only)
#define NCTA    128

// encoder smem: per chunk A 32KB (hi16+lo16) + B 16KB (hi8+lo8) = 48KB x3
#define BUFB   49152
#define SMEMB  (3 * BUFB)
// gx smem: B resident 64KB + A 3x32KB
#define GXSMEM (65536 + 3 * 32768)

// ---------------------------------------------------------------------------
// helpers
// ---------------------------------------------------------------------------
__device__ __forceinline__ uint32_t smem_to_u32(const void* p) {
    uint32_t a;
    asm("{ .reg .u64 t; cvta.to.shared.u64 t, %1; cvt.u32.u64 %0, t; }" : "=r"(a) : "l"(p));
    return a;
}

#define CP_ASYNC16(dst, src) \
    asm volatile("cp.async.cg.shared.global [%0], [%1], 16;" \
                 :: "r"(dst), "l"(__cvta_generic_to_global(src)))
#define CP_COMMIT() asm volatile("cp.async.commit_group;" ::: "memory")
#define CP_WAIT1()  asm volatile("cp.async.wait_group 1;" ::: "memory")
#define CP_WAIT0()  asm volatile("cp.async.wait_group 0;" ::: "memory")

#define LDSM4(r, addr) \
    asm volatile("ldmatrix.sync.aligned.m8n8.x4.shared.b16 {%0,%1,%2,%3}, [%4];" \
                 : "=r"((r)[0]), "=r"((r)[1]), "=r"((r)[2]), "=r"((r)[3]) : "r"(addr))

#define MMA16816(d, a, b) \
    asm volatile("mma.sync.aligned.m16n8k16.row.col.f32.bf16.bf16.f32 " \
                 "{%0,%1,%2,%3}, {%4,%5,%6,%7}, {%8,%9}, {%0,%1,%2,%3};" \
                 : "+f"((d)[0]), "+f"((d)[1]), "+f"((d)[2]), "+f"((d)[3]) \
                 : "r"((a)[0]), "r"((a)[1]), "r"((a)[2]), "r"((a)[3]), \
                   "r"((b)[0]), "r"((b)[1]))

// ---------------------------------------------------------------------------
// device scratch
// ---------------------------------------------------------------------------
__device__ __align__(256) __nv_bfloat16 g_W_hi[4096 * KTOT];
__device__ __align__(256) __nv_bfloat16 g_W_lo[4096 * KTOT];
__device__ __align__(256) __nv_bfloat16 g_x_hi[(size_t)T_STEPS * MPAD * INPUTD];
__device__ __align__(256) __nv_bfloat16 g_x_lo[(size_t)T_STEPS * MPAD * INPUTD];
__device__ __align__(256) __nv_bfloat16 g_hA_hi[2][MPAD * HID];
__device__ __align__(256) __nv_bfloat16 g_hA_lo[2][MPAD * HID];
__device__ __align__(256) float g_gx[(size_t)T_STEPS * MPAD * 4096];   // x @ Wih^T, fp32
__device__ __align__(16) float g_c[MPAD * HID];
__device__ __align__(16) float g_bias[4 * HID];

__device__ __align__(16) float g_u[OUTD];
__device__ __align__(16) float g_hdec[HID];
__device__ __align__(16) float g_comb[HID];
__device__ __align__(16) float g_gi[3 * HID];
__device__ __align__(16) float g_gh[3 * HID];
__device__ __align__(16) float g_v[HID + OUTD];    // [u; hdec]
__device__ __align__(16) float g_v2[HID + OUTD];   // [u; applied]
__device__ float g_sc[WW];
__device__ float g_aw[WW];

__device__ unsigned g_bcnt = 0;
__device__ volatile unsigned g_bgen = 0;

__device__ __forceinline__ void gbar(unsigned nctas) {
    __syncthreads();
    if (threadIdx.x == 0) {
        __threadfence();
        unsigned gen = g_bgen;
        if (atomicAdd(&g_bcnt, 1u) == nctas - 1u) {
            g_bcnt = 0;
            __threadfence();
            g_bgen = gen + 1u;
        } else {
            while (g_bgen == gen) __nanosleep(32);
        }
        __threadfence();
    }
    __syncthreads();
}

__device__ __forceinline__ float sigf(float x)  { return __fdividef(1.f, 1.f + __expf(-x)); }
__device__ __forceinline__ float tanhf_fast(float x) { return 1.f - __fdividef(2.f, __expf(2.f * x) + 1.f); }
__device__ __forceinline__ float warp_red(float s) {
#pragma unroll
    for (int o = 16; o; o >>= 1) s += __shfl_down_sync(0xffffffffu, s, o);
    return s;
}
__device__ __forceinline__ float ctx_at(size_t idx) {
    return __bfloat162float(g_hA_hi[0][idx]) + __bfloat162float(g_hA_lo[0][idx]);
}

// ---------------------------------------------------------------------------
// fragment machinery (32m x 32n warp tile, bf16x3)
// ---------------------------------------------------------------------------
struct Frag {
    uint32_t ah[2][4], al[2][4], bh[4][2], bl[4][2];
};

__device__ __forceinline__ void load_frags(Frag& f, uint32_t Ah, uint32_t Al,
                                           uint32_t Bh, uint32_t Bl,
                                           int ks, int wr, int wc, int lane) {
#pragma unroll
    for (int mt = 0; mt < 2; mt++) {
        int r = wr * 32 + mt * 16 + (lane & 15);
        uint32_t ch = ((uint32_t)((ks * 2 + (lane >> 4)) ^ (r & 7))) << 4;
        LDSM4(f.ah[mt], Ah + r * 128 + ch);
        LDSM4(f.al[mt], Al + r * 128 + ch);
    }
#pragma unroll
    for (int gp = 0; gp < 2; gp++) {
        int rn = (gp * 2 + (lane >> 4)) * 16 + wc * 8 + (lane & 7);
        uint32_t ch = ((uint32_t)((ks * 2 + ((lane >> 3) & 1)) ^ (rn & 7))) << 4;
        LDSM4(&f.bh[gp * 2][0], Bh + rn * 128 + ch);
        LDSM4(&f.bl[gp * 2][0], Bl + rn * 128 + ch);
    }
}

__device__ __forceinline__ void do_mmas(float (&acc)[2][4][4], const Frag& f) {
#pragma unroll
    for (int mt = 0; mt < 2; mt++)
#pragma unroll
        for (int q = 0; q < 4; q++) {
            MMA16816(acc[mt][q], f.ah[mt], f.bh[q]);
            MMA16816(acc[mt][q], f.ah[mt], f.bl[q]);
            MMA16816(acc[mt][q], f.al[mt], f.bh[q]);
        }
}

// ---------------------------------------------------------------------------
// init / convert
// ---------------------------------------------------------------------------
__global__ void k_init(const float* __restrict__ bih, const float* __restrict__ bhh) {
    int i = blockIdx.x * blockDim.x + threadIdx.x;
    int n = MPAD * HID;
    __nv_bfloat16 z = __float2bfloat16(0.f);
    for (int j = i; j < n; j += gridDim.x * blockDim.x) {
        g_c[j] = 0.f;
        g_hA_hi[0][j] = z; g_hA_hi[1][j] = z;
        g_hA_lo[0][j] = z; g_hA_lo[1][j] = z;
    }
    if (i < 4 * HID) g_bias[i] = bih[i] + bhh[i];
}

__global__ void k_conv_w(const float* __restrict__ Whh, const float* __restrict__ Wih) {
    size_t i = (size_t)blockIdx.x * blockDim.x + threadIdx.x;
    if (i >= (size_t)4096 * KTOT) return;
    int r = (int)(i / KTOT);
    int k = (int)(i % KTOT);
    float v = (k < HID) ? Whh[(size_t)r * HID + k] : Wih[(size_t)r * INPUTD + (k - HID)];
    __nv_bfloat16 hi = __float2bfloat16(v);
    g_W_hi[i] = hi;
    g_W_lo[i] = __float2bfloat16(v - __bfloat162float(hi));
}

__global__ void k_conv_x(const float* __restrict__ data) {
    size_t i = (size_t)blockIdx.x * blockDim.x + threadIdx.x;
    if (i >= (size_t)T_STEPS * MPAD * INPUTD) return;
    int k = (int)(i % INPUTD);
    int b = (int)((i / INPUTD) % MPAD);
    int t = (int)(i / ((size_t)MPAD * INPUTD));
    float v = (b < BATCH) ? data[((size_t)t * BATCH + b) * INPUTD + k] : 0.f;
    __nv_bfloat16 hi = __float2bfloat16(v);
    g_x_hi[i] = hi;
    g_x_lo[i] = __float2bfloat16(v - __bfloat162float(hi));
}

// ---------------------------------------------------------------------------
// k_gx: Gx[t] = x_t @ Wih^T for all t.  128 persistent CTAs, weights resident.
// ---------------------------------------------------------------------------
__global__ __launch_bounds__(256, 1) void k_gx() {
    extern __shared__ __align__(128) char smem[];
    const uint32_t sb  = smem_to_u32(smem);
    const uint32_t sbB = sb;
    const uint32_t sbA = sb + 65536;
    const int tid  = threadIdx.x;
    const int lane = tid & 31;
    const int wid  = tid >> 5;
    const int wr   = wid & 3;
    const int wc   = wid >> 2;
    const int n0   = (blockIdx.x & 63) * 16;
    const int m0   = (blockIdx.x >> 6) * 128;
    const int rowq = lane >> 2;
    const int col2 = (lane & 3) * 2;

    // resident B: Wih K-slices (k = 1024 + ci*64), 4 chunks of 16KB (hi8+lo8)
#pragma unroll
    for (int i = tid; i < 2048; i += 256) {
        int ci = i >> 9, r = (i >> 3) & 63, ch = i & 7;
        int wrow = (r >> 4) * HID + n0 + (r & 15);
        size_t off = (size_t)wrow * KTOT + HID + ci * 64 + ch * 8;
        uint32_t dst = sbB + ci * 16384 + r * 128 + (((uint32_t)(ch ^ (r & 7))) << 4);
        CP_ASYNC16(dst, g_W_hi + off);
        CP_ASYNC16(dst + 8192, g_W_lo + off);
    }
    CP_COMMIT();

    auto loadA = [&](int lin) {
        int t = lin >> 2, ci = lin & 3;
        uint32_t base = sbA + (lin % 3) * 32768;
#pragma unroll
        for (int i = tid; i < 1024; i += 256) {
            int r = i >> 3, ch = i & 7;
            size_t off = ((size_t)t * MPAD + m0 + r) * INPUTD + ci * 64 + ch * 8;
            uint32_t dst = base + r * 128 + (((uint32_t)(ch ^ (r & 7))) << 4);
            CP_ASYNC16(dst, g_x_hi + off);
            CP_ASYNC16(dst + 16384, g_x_lo + off);
        }
        CP_COMMIT();
    };

    loadA(0); loadA(1);
    Frag fr[2];

    for (int t = 0; t < T_STEPS; t++) {
        float acc[2][4][4];
#pragma unroll
        for (int mt = 0; mt < 2; mt++)
#pragma unroll
            for (int q = 0; q < 4; q++)
#pragma unroll
                for (int j = 0; j < 4; j++) acc[mt][q][j] = 0.f;

        for (int ci = 0; ci < 4; ci++) {
            int lin = t * 4 + ci;
            if (lin == T_STEPS * 4 - 1) { CP_WAIT0(); } else { CP_WAIT1(); }
            __syncthreads();
            if (lin + 2 < T_STEPS * 4) loadA(lin + 2);

            const uint32_t Ab = sbA + (lin % 3) * 32768;
            const uint32_t Ah = Ab, Al = Ab + 16384;
            const uint32_t Bh = sbB + ci * 16384, Bl = Bh + 8192;

            load_frags(fr[0], Ah, Al, Bh, Bl, 0, wr, wc, lane);
#pragma unroll
            for (int ks = 0; ks < 4; ks++) {
                if (ks < 3) load_frags(fr[(ks + 1) & 1], Ah, Al, Bh, Bl, ks + 1, wr, wc, lane);
                do_mmas(acc, fr[ks & 1]);
            }
        }

        float* gx = g_gx + (size_t)t * MPAD * 4096;
#pragma unroll
        for (int mt = 0; mt < 2; mt++)
#pragma unroll
            for (int rp = 0; rp < 2; rp++) {
                int m = m0 + wr * 32 + mt * 16 + rowq + rp * 8;
#pragma unroll
                for (int q = 0; q < 4; q++) {
                    int col = q * 1024 + n0 + wc * 8 + col2;
                    *(float2*)&gx[(size_t)m * 4096 + col] =
                        make_float2(acc[mt][q][rp * 2], acc[mt][q][rp * 2 + 1]);
                }
            }
    }
}

// ---------------------------------------------------------------------------
// k_enc: persistent, 240 LSTM steps, K=1024 (h only), acc init from Gx.
// 128 CTAs x 256 thr (8 warps, 32x32 warp tiles).
// ---------------------------------------------------------------------------
__global__ __launch_bounds__(256, 1) void k_enc() {
    extern __shared__ __align__(128) char smem[];
    const uint32_t sb = smem_to_u32(smem);
    const int tid  = threadIdx.x;
    const int lane = tid & 31;
    const int wid  = tid >> 5;
    const int wr   = wid & 3;
    const int wc   = wid >> 2;
    const int n0   = (blockIdx.x & 63) * 16;
    const int m0   = (blockIdx.x >> 6) * 128;
    const int rowq = lane >> 2;
    const int col2 = (lane & 3) * 2;

    for (int t = 0; t < T_STEPS; t++) {
        const int par = t & 1;
        const __nv_bfloat16* __restrict__ hHi = g_hA_hi[par];
        const __nv_bfloat16* __restrict__ hLo = g_hA_lo[par];

        auto load_chunk = [&](int c) {
            const uint32_t base = sb + (c % 3) * BUFB;
            const int k0 = c * KCH;
#pragma unroll
            for (int i = tid; i < 1024; i += 256) {
                int r = i >> 3, ch = i & 7;
                uint32_t dst = base + r * 128 + (((uint32_t)(ch ^ (r & 7))) << 4);
                size_t off = (size_t)(m0 + r) * HID + k0 + ch * 8;
                CP_ASYNC16(dst,         hHi + off);
                CP_ASYNC16(dst + 16384, hLo + off);
            }
#pragma unroll
            for (int i = tid; i < 512; i += 256) {
                int r = i >> 3, ch = i & 7;
                uint32_t dst = base + 32768 + r * 128 + (((uint32_t)(ch ^ (r & 7))) << 4);
                int wrow = (r >> 4) * HID + n0 + (r & 15);
                size_t off = (size_t)wrow * KTOT + k0 + ch * 8;
                CP_ASYNC16(dst,        g_W_hi + off);
                CP_ASYNC16(dst + 8192, g_W_lo + off);
            }
            CP_COMMIT();
        };

        load_chunk(0);
        load_chunk(1);

        // init accumulators from precomputed x @ Wih^T
        float acc[2][4][4];
        {
            const float* gx = g_gx + (size_t)t * MPAD * 4096;
#pragma unroll
            for (int mt = 0; mt < 2; mt++)
#pragma unroll
                for (int rp = 0; rp < 2; rp++) {
                    int m = m0 + wr * 32 + mt * 16 + rowq + rp * 8;
#pragma unroll
                    for (int q = 0; q < 4; q++) {
                        int col = q * 1024 + n0 + wc * 8 + col2;
                        float2 v = *(const float2*)&gx[(size_t)m * 4096 + col];
                        acc[mt][q][rp * 2]     = v.x;
                        acc[mt][q][rp * 2 + 1] = v.y;
                    }
                }
        }

        Frag fr[2];
        for (int c = 0; c < NCH_H; c++) {
            if (c == NCH_H - 1) { CP_WAIT0(); } else { CP_WAIT1(); }
            __syncthreads();
            if (c + 2 < NCH_H) load_chunk(c + 2);

            const uint32_t base = sb + (c % 3) * BUFB;
            const uint32_t Ah = base, Al = base + 16384, Bh = base + 32768, Bl = base + 40960;

            load_frags(fr[0], Ah, Al, Bh, Bl, 0, wr, wc, lane);
#pragma unroll
            for (int ks = 0; ks < 4; ks++) {
                if (ks < 3) load_frags(fr[(ks + 1) & 1], Ah, Al, Bh, Bl, ks + 1, wr, wc, lane);
                do_mmas(acc, fr[ks & 1]);
            }
        }

        // fused LSTM gate epilogue
        __nv_bfloat16* __restrict__ oHi = g_hA_hi[par ^ 1];
        __nv_bfloat16* __restrict__ oLo = g_hA_lo[par ^ 1];
#pragma unroll
        for (int mt = 0; mt < 2; mt++)
#pragma unroll
            for (int rp = 0; rp < 2; rp++) {
                int m = m0 + wr * 32 + mt * 16 + rowq + rp * 8;
                if (m < BATCH) {
                    int n = n0 + wc * 8 + col2;
                    size_t idx = (size_t)m * HID + n;
                    float2 cold = *(float2*)&g_c[idx];
                    float2 bi = *(const float2*)&g_bias[n];
                    float2 bf = *(const float2*)&g_bias[HID + n];
                    float2 bg = *(const float2*)&g_bias[2 * HID + n];
                    float2 bo = *(const float2*)&g_bias[3 * HID + n];
                    float h[2], cn[2];
#pragma unroll
                    for (int j = 0; j < 2; j++) {
                        float gi = acc[mt][0][rp * 2 + j] + (j ? bi.y : bi.x);
                        float gf = acc[mt][1][rp * 2 + j] + (j ? bf.y : bf.x);
                        float gg = acc[mt][2][rp * 2 + j] + (j ? bg.y : bg.x);
                        float go = acc[mt][3][rp * 2 + j] + (j ? bo.y : bo.x);
                        cn[j] = sigf(gf) * (j ? cold.y : cold.x) + sigf(gi) * tanhf_fast(gg);
                        h[j]  = sigf(go) * tanhf_fast(cn[j]);
                    }
                    *(float2*)&g_c[idx] = make_float2(cn[0], cn[1]);
                    __nv_bfloat16 h0 = __float2bfloat16(h[0]);
                    __nv_bfloat16 h1 = __float2bfloat16(h[1]);
                    *(__nv_bfloat162*)&oHi[idx] = __halves2bfloat162(h0, h1);
                    *(__nv_bfloat162*)&oLo[idx] = __halves2bfloat162(
                        __float2bfloat16(h[0] - __bfloat162float(h0)),
                        __float2bfloat16(h[1] - __bfloat162float(h1)));
                }
            }

        gbar(NCTA);
    }
}

// ---------------------------------------------------------------------------
// k_dec: persistent decoder, 128 CTAs x 256 thr, float4 matvecs.
// ---------------------------------------------------------------------------
__global__ __launch_bounds__(256, 1) void k_dec(
    const float* __restrict__ attn_W, const float* __restrict__ attn_b,
    const float* __restrict__ comb_W, const float* __restrict__ comb_b,
    const float* __restrict__ gWih,   const float* __restrict__ gWhh,
    const float* __restrict__ gbih,   const float* __restrict__ gbhh,
    const float* __restrict__ out_W,  const float* __restrict__ out_b,
    float* __restrict__ outp)
{
    const int tid  = threadIdx.x;
    const int bid  = blockIdx.x;
    const int lane = tid & 31;
    const int warp = tid >> 5;
    const int gw   = bid * 8 + warp;   // 0..1023

    if (bid == 0) {
        for (int i = tid; i < HID; i += 256) {
            float v = ctx_at((size_t)(BATCH - 1) * HID + i);
            g_hdec[i] = v;
            g_v[OUTD + i] = v;
        }
        if (tid < OUTD) { g_u[tid] = 0.125f; g_v[tid] = 0.125f; g_v2[tid] = 0.125f; }
    }
    gbar(NCTA);

    for (int step = 0; step < NSTEPS; step++) {
        // ph1: attention scores
        if (gw < WW) {
            const float4* row = (const float4*)(attn_W + (size_t)gw * (HID + OUTD));
            const float4* v   = (const float4*)g_v;
            float s = 0.f;
            for (int k = lane; k < (HID + OUTD) / 4; k += 32) {
                float4 w = row[k], x = v[k];
                s += w.x * x.x + w.y * x.y + w.z * x.z + w.w * x.w;
            }
            s = warp_red(s);
            if (!lane) g_sc[gw] = s + attn_b[gw];
        }
        gbar(NCTA);

        // ph2: softmax (CTA 0)
        if (bid == 0) {
            __shared__ float rbuf[8];
            float x = (tid < WW) ? g_sc[tid] : -1e30f;
            float mx = x;
#pragma unroll
            for (int o = 16; o; o >>= 1) mx = fmaxf(mx, __shfl_xor_sync(0xffffffffu, mx, o));
            if (!lane) rbuf[warp] = mx;
            __syncthreads();
            float bm = rbuf[0];
#pragma unroll
            for (int i = 1; i < 8; i++) bm = fmaxf(bm, rbuf[i]);
            float e = (tid < WW) ? __expf(x - bm) : 0.f;
            float sm = e;
#pragma unroll
            for (int o = 16; o; o >>= 1) sm += __shfl_xor_sync(0xffffffffu, sm, o);
            __syncthreads();
            if (!lane) rbuf[warp] = sm;
            __syncthreads();
            float tot = 0.f;
#pragma unroll
            for (int i = 0; i < 8; i++) tot += rbuf[i];
            if (tid < WW) g_aw[tid] = e / tot;
        }
        gbar(NCTA);

        // ph3: applied = aw @ ctx -> g_v2[OUTD + n]
        {
            int n = gw;
            float s = 0.f;
            for (int j = lane; j < WW; j += 32) s += g_aw[j] * ctx_at((size_t)j * HID + n);
            s = warp_red(s);
            if (!lane) g_v2[OUTD + n] = s;
        }
        gbar(NCTA);

        // ph4: comb = relu(comb_W @ v2 + b)
        {
            const float4* row = (const float4*)(comb_W + (size_t)gw * (HID + OUTD));
            const float4* v   = (const float4*)g_v2;
            float s = 0.f;
            for (int k = lane; k < (HID + OUTD) / 4; k += 32) {
                float4 w = row[k], x = v[k];
                s += w.x * x.x + w.y * x.y + w.z * x.z + w.w * x.w;
            }
            s = warp_red(s);
            if (!lane) g_comb[gw] = fmaxf(s + comb_b[gw], 0.f);
        }
        gbar(NCTA);

        // ph5: gi / gh (6144 rows over 1024 warps)
        for (int rr = gw; rr < 6 * HID; rr += 1024) {
            const float4* row;
            const float4* v;
            if (rr < 3 * HID) {
                row = (const float4*)(gWih + (size_t)rr * HID);
                v = (const float4*)g_comb;
            } else {
                row = (const float4*)(gWhh + (size_t)(rr - 3 * HID) * HID);
                v = (const float4*)g_hdec;
            }
            float s = 0.f;
            for (int k = lane; k < HID / 4; k += 32) {
                float4 w = row[k], x = v[k];
                s += w.x * x.x + w.y * x.y + w.z * x.z + w.w * x.w;
            }
            s = warp_red(s);
            if (!lane) {
                if (rr < 3 * HID) g_gi[rr] = s + gbih[rr];
                else              g_gh[rr - 3 * HID] = s + gbhh[rr - 3 * HID];
            }
        }
        gbar(NCTA);

        // ph6: gate update + output head + next-step vector (CTA 0)
        if (bid == 0) {
            for (int n = tid; n < HID; n += 256) {
                float r  = sigf(g_gi[n] + g_gh[n]);
                float z  = sigf(g_gi[HID + n] + g_gh[HID + n]);
                float nn = tanhf_fast(g_gi[2 * HID + n] + r * g_gh[2 * HID + n]);
                g_hdec[n] = (1.f - z) * nn + z * g_hdec[n];
            }
            __syncthreads();
            __shared__ float lg[OUTD];
            if (warp < OUTD) {
                const float4* row = (const float4*)(out_W + (size_t)warp * HID);
                const float4* v   = (const float4*)g_hdec;
                float s = 0.f;
                for (int k = lane; k < HID / 4; k += 32) {
                    float4 w = row[k], x = v[k];
                    s += w.x * x.x + w.y * x.y + w.z * x.z + w.w * x.w;
                }
                s = warp_red(s);
                if (!lane) lg[warp] = s + out_b[warp];
            }
            __syncthreads();
            if (tid == 0) {
                float mx = -1e30f;
#pragma unroll
                for (int i = 0; i < OUTD; i++) mx = fmaxf(mx, lg[i]);
                float sum = 0.f;
#pragma unroll
                for (int i = 0; i < OUTD; i++) sum += __expf(lg[i] - mx);
                float lse = mx + __logf(sum);
#pragma unroll
                for (int i = 0; i < OUTD; i++) {
                    float lp = lg[i] - lse;
                    outp[step * OUTD + i] = lp;
                    g_u[i] = lp;
                }
            }
            __syncthreads();
            for (int i = tid; i < HID; i += 256) g_v[OUTD + i] = g_hdec[i];
            if (tid < OUTD) { float u = g_u[tid]; g_v[tid] = u; g_v2[tid] = u; }
        }
        gbar(NCTA);
    }
}

// ---------------------------------------------------------------------------
// launch
// ---------------------------------------------------------------------------
extern "C" void kernel_launch(void* const* d_in, const int* in_sizes, int n_in,
                              void* d_out, int out_size) {
    const float* data     = (const float*)d_in[0];
    const float* enc_Wih  = (const float*)d_in[1];
    const float* enc_Whh  = (const float*)d_in[2];
    const float* enc_bih  = (const float*)d_in[3];
    const float* enc_bhh  = (const float*)d_in[4];
    const float* attn_W   = (const float*)d_in[5];
    const float* attn_b   = (const float*)d_in[6];
    const float* comb_W   = (const float*)d_in[7];
    const float* comb_b   = (const float*)d_in[8];
    const float* gru_Wih  = (const float*)d_in[9];
    const float* gru_Whh  = (const float*)d_in[10];
    const float* gru_bih  = (const float*)d_in[11];
    const float* gru_bhh  = (const float*)d_in[12];
    const float* out_W    = (const float*)d_in[13];
    const float* out_b    = (const float*)d_in[14];
    float* out = (float*)d_out;

    cudaFuncSetAttribute(k_enc, cudaFuncAttributeMaxDynamicSharedMemorySize, SMEMB);
    cudaFuncSetAttribute(k_gx,  cudaFuncAttributeMaxDynamicSharedMemorySize, GXSMEM);

    k_init<<<1024, 256>>>(enc_bih, enc_bhh);
    k_conv_w<<<(4096 * KTOT + 255) / 256, 256>>>(enc_Whh, enc_Wih);
    k_conv_x<<<(T_STEPS * MPAD * INPUTD + 255) / 256, 256>>>(data);

    k_gx<<<NCTA, 256, GXSMEM>>>();
    k_enc<<<NCTA, 256, SMEMB>>>();

    k_dec<<<NCTA, 256>>>(attn_W, attn_b, comb_W, comb_b,
                         gru_Wih, gru_Whh, gru_bih, gru_bhh,
                         out_W, out_b, out);
}